// round 5
// baseline (speedup 1.0000x reference)
#include <cuda_runtime.h>
#include <math.h>

#define DIMD 128
#define PMAX 3136

// Scratch: RECIPROCAL of diag(inv(b_covs[p]))[d], stored [D][P].
__device__ float g_rdinv[DIMD * PMAX];

// ---------------------------------------------------------------------------
// Phase A: BLOCKED symmetric sweep (rank-8 steps) on the lower triangle.
// Sweep of block K (8 indices):
//   M_KK' = -M_KK^{-1}
//   M_iK' = M_iK * M_KK^{-1}                    (i not in K)
//   M_ij' = M_ij - M_iK * M_KK^{-1} * M_Kj      (i,j not in K)
// After sweeping all 16 blocks, M = -inv(A); emit -1/diag.
//
// Tile layout: 272 threads own 4x8 register tiles of the lower triangle
// (tile grid 32 row-blocks x 16 col-blocks; col-block c has rows 2c..31).
// Straddle-tile mirrored upper entries evolve correctly by symmetry (the
// rank-8 update L[i].C[j] is symmetric in i<->j since D^-1 is symmetric).
//
// Per block step: stage panel C (done at end of prev step) -> warp 0 sweeps
// the 8x8 pivot block via shuffles -> 128 threads build L = C*D^-1 ->
// everyone does the 256-FFMA trailing update + overwrites swept tiles.
// 3 barriers per step, 16 steps.
// ---------------------------------------------------------------------------
__global__ __launch_bounds__(288, 2)
void sweep_diag_kernel(const float* __restrict__ covs, int P)
{
    int p = blockIdx.x;
    const float* A = covs + (size_t)p * DIMD * DIMD;

    int tid = threadIdx.x;
    bool active = tid < 272;

    // tid -> (r, c): for c in 0..15, r in 2c..31
    int t = active ? tid : 0;
    int c = 0;
#pragma unroll 1
    while (t >= (32 - 2 * c)) { t -= (32 - 2 * c); c++; }
    int r = 2 * c + t;
    int R0 = r << 2;     // 4 rows
    int C0 = c << 3;     // 8 cols

    float T[4][8];
    if (active) {
#pragma unroll
        for (int a = 0; a < 4; a++) {
            const float4* src = reinterpret_cast<const float4*>(A + (size_t)(R0 + a) * DIMD + C0);
            float4 v0 = src[0], v1 = src[1];
            T[a][0]=v0.x; T[a][1]=v0.y; T[a][2]=v0.z; T[a][3]=v0.w;
            T[a][4]=v1.x; T[a][5]=v1.y; T[a][6]=v1.z; T[a][7]=v1.w;
        }
    }

    __shared__ float Cp[2][DIMD][8];   // panel M[:,Kq], double-buffered
    __shared__ float Lp[DIMD][8];      // L = C * D^-1
    __shared__ float G[8][8];          // -D^-1 (swept pivot block)

    // Initial staging of panel for q=0 (col-block 0 tiles cover rows 0..127).
    if (active && c == 0) {
#pragma unroll
        for (int a = 0; a < 4; a++)
#pragma unroll
            for (int b = 0; b < 8; b++)
                Cp[0][R0 + a][b] = T[a][b];
    }
    __syncthreads();

#pragma unroll 1
    for (int q = 0; q < 16; q++) {
        int buf = q & 1;
        int q8  = q << 3;

        // ---- warp 0: sweep the 8x8 pivot block (row-per-lane, shuffles) ----
        if (tid < 32) {
            int lr = tid & 7;
            float d[8];
            {
                const float4* dr = reinterpret_cast<const float4*>(&Cp[buf][q8 + lr][0]);
                float4 u0 = dr[0], u1 = dr[1];
                d[0]=u0.x; d[1]=u0.y; d[2]=u0.z; d[3]=u0.w;
                d[4]=u1.x; d[5]=u1.y; d[6]=u1.z; d[7]=u1.w;
            }
#pragma unroll
            for (int k = 0; k < 8; k++) {
                float pvr = 1.0f / __shfl_sync(0xffffffffu, d[k], k);
                float s[8];
#pragma unroll
                for (int j = 0; j < 8; j++)
                    s[j] = __shfl_sync(0xffffffffu, d[j], k) * pvr;
                bool isk = (lr == k);
                float fk = d[k];
#pragma unroll
                for (int j = 0; j < 8; j++) {
                    if (j == k) continue;
                    d[j] = isk ? s[j] : fmaf(-fk, s[j], d[j]);
                }
                d[k] = isk ? -pvr : fk * pvr;
            }
            if (tid < 8) {
                float4* gw = reinterpret_cast<float4*>(&G[lr][0]);
                gw[0] = make_float4(d[0], d[1], d[2], d[3]);
                gw[1] = make_float4(d[4], d[5], d[6], d[7]);
            }
        }
        __syncthreads();

        // ---- L rows: L[i][:] = C[i][:] * D^-1 = -C[i][:] * G ----
        if (tid < DIMD) {
            float cr[8];
            {
                const float4* cc = reinterpret_cast<const float4*>(&Cp[buf][tid][0]);
                float4 v0 = cc[0], v1 = cc[1];
                cr[0]=v0.x; cr[1]=v0.y; cr[2]=v0.z; cr[3]=v0.w;
                cr[4]=v1.x; cr[5]=v1.y; cr[6]=v1.z; cr[7]=v1.w;
            }
            float acc[8];
#pragma unroll
            for (int b = 0; b < 8; b++) acc[b] = 0.0f;
#pragma unroll
            for (int kq = 0; kq < 8; kq++)
#pragma unroll
                for (int b = 0; b < 8; b++)
                    acc[b] = fmaf(cr[kq], G[kq][b], acc[b]);
            float4* lw = reinterpret_cast<float4*>(&Lp[tid][0]);
            lw[0] = make_float4(-acc[0], -acc[1], -acc[2], -acc[3]);
            lw[1] = make_float4(-acc[4], -acc[5], -acc[6], -acc[7]);
        }
        __syncthreads();

        // ---- trailing rank-8 update + overwrite swept tiles + stage next ----
        if (active) {
            float Lr[4][8];
#pragma unroll
            for (int a = 0; a < 4; a++) {
                const float4* lr4 = reinterpret_cast<const float4*>(&Lp[R0 + a][0]);
                float4 u0 = lr4[0], u1 = lr4[1];
                Lr[a][0]=u0.x; Lr[a][1]=u0.y; Lr[a][2]=u0.z; Lr[a][3]=u0.w;
                Lr[a][4]=u1.x; Lr[a][5]=u1.y; Lr[a][6]=u1.z; Lr[a][7]=u1.w;
            }
#pragma unroll
            for (int b = 0; b < 8; b++) {
                float cb[8];
                const float4* cb4 = reinterpret_cast<const float4*>(&Cp[buf][C0 + b][0]);
                float4 w0 = cb4[0], w1 = cb4[1];
                cb[0]=w0.x; cb[1]=w0.y; cb[2]=w0.z; cb[3]=w0.w;
                cb[4]=w1.x; cb[5]=w1.y; cb[6]=w1.z; cb[7]=w1.w;
#pragma unroll
                for (int a = 0; a < 4; a++)
#pragma unroll
                    for (int kq = 0; kq < 8; kq++)
                        T[a][b] = fmaf(-Lr[a][kq], cb[kq], T[a][b]);
            }

            // Overwrite swept rows/cols with their new values.
            if (c == q) {
                if (r == 2 * q || r == 2 * q + 1) {
                    // diagonal block: M_KK' = -D^-1 = G
#pragma unroll
                    for (int a = 0; a < 4; a++)
#pragma unroll
                        for (int b = 0; b < 8; b++)
                            T[a][b] = G[R0 + a - q8][b];
                } else {
                    // panel: M_iK' = L[i]
#pragma unroll
                    for (int a = 0; a < 4; a++)
#pragma unroll
                        for (int b = 0; b < 8; b++)
                            T[a][b] = Lp[R0 + a][b];
                }
            } else if (r == 2 * q || r == 2 * q + 1) {
                // row block (c < q): M_Kj' = L[j]^T
#pragma unroll
                for (int a = 0; a < 4; a++)
#pragma unroll
                    for (int b = 0; b < 8; b++)
                        T[a][b] = Lp[C0 + b][R0 + a - q8];
            }

            // Stage panel for the next block step into the other buffer.
            if (q < 15) {
                int qn = q + 1, nb = buf ^ 1, qn8 = qn << 3;
                if (c == qn) {
#pragma unroll
                    for (int a = 0; a < 4; a++)
#pragma unroll
                        for (int b = 0; b < 8; b++)
                            Cp[nb][R0 + a][b] = T[a][b];
                } else if (r == 2 * qn || r == 2 * qn + 1) {
#pragma unroll
                    for (int a = 0; a < 4; a++)
#pragma unroll
                        for (int b = 0; b < 8; b++)
                            Cp[nb][C0 + b][R0 + a - qn8] = T[a][b];
                }
            }
        }
        __syncthreads();
    }

    // M = -inv(A); emit reciprocal of diag(inv) = -1/T_diag.
    if (active && r <= 2 * c + 1) {
#pragma unroll
        for (int a = 0; a < 4; a++)
#pragma unroll
            for (int b = 0; b < 8; b++)
                if (R0 + a == C0 + b)
                    g_rdinv[(size_t)(R0 + a) * P + p] = -1.0f / T[a][b];
    }
}

// ---------------------------------------------------------------------------
// Phase B: streaming whitening + cosine similarity.
// 4 lanes cooperate per (b,p) output (32 d's each) + shfl reduction.
// g_rdinv already holds 1/diag(inv) => pure multiply, no divisions.
// ---------------------------------------------------------------------------
__global__ void ace_kernel(const float* __restrict__ X,
                           const float* __restrict__ bmean,
                           const float* __restrict__ covs,
                           const float* __restrict__ sig,
                           const int* __restrict__ covtype,
                           float* __restrict__ out,
                           int B, int P)
{
    int gtid = blockIdx.x * blockDim.x + threadIdx.x;
    int idx  = gtid >> 2;            // output index (b*P + p)
    int sub  = gtid & 3;             // which quarter of D this lane handles
    if (idx >= B * P) return;
    int b = idx / P;
    int p = idx - b * P;
    int ct = *covtype;

    float ww = 0.f, ws = 0.f, ss = 0.f;

    if (ct == 0) {
        // Full-covariance fallback: each lane does 32 of the 128 output dims.
        for (int m = sub * 32; m < sub * 32 + 32; m++) {
            float w = 0.f;
            const float* cr = covs + ((size_t)p * DIMD + m) * DIMD;
            for (int d = 0; d < DIMD; d++) {
                float xc = X[((size_t)b * DIMD + d) * P + p] - bmean[(size_t)d * P + p];
                w = fmaf(xc, cr[d], w);
            }
            float s = sig[(size_t)m * P + p];
            ww = fmaf(w, w, ww);
            ws = fmaf(w, s, ws);
            ss = fmaf(s, s, ss);
        }
    } else {
        bool use_diag = (ct == 1);
        int d0 = sub * 32;
#pragma unroll 16
        for (int i = 0; i < 32; i++) {
            int d = d0 + i;
            float xc = X[((size_t)b * DIMD + d) * P + p] - bmean[(size_t)d * P + p];
            float s  = sig[(size_t)d * P + p];
            float w  = use_diag ? (xc * g_rdinv[(size_t)d * P + p]) : xc;
            ww = fmaf(w, w, ww);
            ws = fmaf(w, s, ws);
            ss = fmaf(s, s, ss);
        }
    }

#pragma unroll
    for (int m = 1; m < 4; m <<= 1) {
        ww += __shfl_xor_sync(0xFFFFFFFF, ww, m);
        ws += __shfl_xor_sync(0xFFFFFFFF, ws, m);
        ss += __shfl_xor_sync(0xFFFFFFFF, ss, m);
    }

    if (sub == 0) {
        float denom = fmaxf(sqrtf(ww), 1e-12f) * fmaxf(sqrtf(ss), 1e-12f);
        out[idx] = ws / denom;
    }
}

extern "C" void kernel_launch(void* const* d_in, const int* in_sizes, int n_in,
                              void* d_out, int out_size)
{
    const float* X      = (const float*)d_in[0];
    const float* bmean  = (const float*)d_in[1];
    const float* covs   = (const float*)d_in[2];
    const float* sig    = (const float*)d_in[3];
    const int*   ctype  = (const int*)d_in[4];
    float*       out    = (float*)d_out;

    int P = in_sizes[2] / (DIMD * DIMD);           // 3136
    int B = in_sizes[0] / (DIMD * P);              // 32

    sweep_diag_kernel<<<P, 288>>>(covs, P);

    int total = B * P * 4;                         // 4 lanes per output
    ace_kernel<<<(total + 255) / 256, 256>>>(X, bmean, covs, sig, ctype, out, B, P);
}

// round 6
// speedup vs baseline: 1.2454x; 1.2454x over previous
#include <cuda_runtime.h>
#include <math.h>

#define DIMD 128
#define PMAX 3136

// Scratch: RECIPROCAL of diag(inv(b_covs[p]))[d], stored [D][P].
__device__ float g_rdinv[DIMD * PMAX];

// ---------------------------------------------------------------------------
// Phase A: Gauss-Jordan inversion, TWO pivots per barrier round.
// 16x16 threads, each owns an 8x8 register tile (R2 structure). Per round we
// stage raw columns k,k+1 and raw rows k,k+1; every thread locally corrects
// the second column/row for the first pivot (16 redundant FMA) using the 2x2
// pivot block -- so both pivots complete with ONE __syncthreads (64 rounds
// total instead of 128).
//
// All register-tile indices are compile-time: rounds are unrolled in groups
// of 4 (QI=0..3) so the pivot offset inside the 8-wide block (A0=2*QI) is a
// constant. Only shared-memory indices use runtime k.
// ---------------------------------------------------------------------------

__device__ __forceinline__ void ld8(float (&d)[8], const float* s) {
    const float4* s4 = reinterpret_cast<const float4*>(s);
    float4 v0 = s4[0], v1 = s4[1];
    d[0]=v0.x; d[1]=v0.y; d[2]=v0.z; d[3]=v0.w;
    d[4]=v1.x; d[5]=v1.y; d[6]=v1.z; d[7]=v1.w;
}

template<int QI>
__device__ __forceinline__ void gj2_round(
    float (&T)[8][8],
    float (&colS)[2][2][DIMD], float (&rowS)[2][2][DIMD],
    int rq, int ty, int tx, int R0, int C0)
{
    constexpr int BUF  = QI & 1;
    constexpr int NBUF = BUF ^ 1;
    constexpr int A0   = 2 * QI;           // offset of pivot k0 inside its 8-block
    const int k0 = (rq << 3) + 2 * QI;

    // 2x2 pivot block (broadcast loads).
    float P00 = colS[BUF][0][k0],     P01 = colS[BUF][1][k0];
    float P10 = colS[BUF][0][k0 + 1], P11 = colS[BUF][1][k0 + 1];

    float CI0[8], CI1[8], RJ0[8], RJ1[8];
    ld8(CI0, &colS[BUF][0][R0]);
    ld8(CI1, &colS[BUF][1][R0]);
    ld8(RJ0, &rowS[BUF][0][C0]);
    ld8(RJ1, &rowS[BUF][1][C0]);

    // ---------------- pivot 0 (global index k0) ----------------
    float pv0 = 1.0f / P00;
    float s0[8];
#pragma unroll
    for (int b = 0; b < 8; b++) s0[b] = RJ0[b] * pv0;
#pragma unroll
    for (int a = 0; a < 8; a++)
#pragma unroll
        for (int b = 0; b < 8; b++)
            T[a][b] = fmaf(-CI0[a], s0[b], T[a][b]);

    if (ty == rq) {                        // pivot-row fixup
#pragma unroll
        for (int b = 0; b < 8; b++) T[A0][b] = s0[b];
    }
    if (tx == rq) {                        // pivot-col fixup
#pragma unroll
        for (int a = 0; a < 8; a++) T[a][A0] = -CI0[a] * pv0;
        if (ty == rq) T[A0][A0] = pv0;
    }

    // Correct the second staged column/row for pivot 0.
    float fC = P01 * pv0;                  // M[k0][k0+1]/d0
#pragma unroll
    for (int a = 0; a < 8; a++) CI1[a] = fmaf(-CI0[a], fC, CI1[a]);
#pragma unroll
    for (int b = 0; b < 8; b++) RJ1[b] = fmaf(-P10, s0[b], RJ1[b]);

    float nP11 = fmaf(-P10, fC, P11);      // updated M[k0+1][k0+1]
    float nP01 = fC;                       // swept row value M'[k0][k0+1]
    float nP10 = -P10 * pv0;               // swept col value M'[k0+1][k0]

    // Pivot rows/cols need swept (not generic) values in the staged data.
    if (ty == rq) { CI1[A0] = nP01; CI1[A0 + 1] = nP11; }
    if (tx == rq) { RJ1[A0] = nP10; RJ1[A0 + 1] = nP11; }

    // ---------------- pivot 1 (global index k0+1) ----------------
    float pv1 = 1.0f / nP11;
    float s1[8];
#pragma unroll
    for (int b = 0; b < 8; b++) s1[b] = RJ1[b] * pv1;
#pragma unroll
    for (int a = 0; a < 8; a++)
#pragma unroll
        for (int b = 0; b < 8; b++)
            T[a][b] = fmaf(-CI1[a], s1[b], T[a][b]);

    if (ty == rq) {
#pragma unroll
        for (int b = 0; b < 8; b++) T[A0 + 1][b] = s1[b];
    }
    if (tx == rq) {
#pragma unroll
        for (int a = 0; a < 8; a++) T[a][A0 + 1] = -CI1[a] * pv1;
        if (ty == rq) T[A0 + 1][A0 + 1] = pv1;
    }

    // ---------------- stage next round's columns/rows ----------------
    if (k0 + 2 < DIMD) {
        constexpr int B0N = (QI == 3) ? 0 : (2 * QI + 2);
        const int rqn = rq + ((QI == 3) ? 1 : 0);
        if (tx == rqn) {
#pragma unroll
            for (int a = 0; a < 8; a++) {
                colS[NBUF][0][R0 + a] = T[a][B0N];
                colS[NBUF][1][R0 + a] = T[a][B0N + 1];
            }
        }
        if (ty == rqn) {
#pragma unroll
            for (int b = 0; b < 8; b++) {
                rowS[NBUF][0][C0 + b] = T[B0N][b];
                rowS[NBUF][1][C0 + b] = T[B0N + 1][b];
            }
        }
    }
    __syncthreads();
}

__global__ __launch_bounds__(256, 2)
void inv_diag_kernel(const float* __restrict__ covs, int P)
{
    int p = blockIdx.x;
    const float* A = covs + (size_t)p * DIMD * DIMD;

    int tid = threadIdx.x;
    int ty = tid >> 4;
    int tx = tid & 15;
    int R0 = ty << 3;
    int C0 = tx << 3;

    float T[8][8];
#pragma unroll
    for (int a = 0; a < 8; a++) {
        const float4* src = reinterpret_cast<const float4*>(A + (size_t)(R0 + a) * DIMD + C0);
        float4 v0 = src[0], v1 = src[1];
        T[a][0]=v0.x; T[a][1]=v0.y; T[a][2]=v0.z; T[a][3]=v0.w;
        T[a][4]=v1.x; T[a][5]=v1.y; T[a][6]=v1.z; T[a][7]=v1.w;
    }

    __shared__ float colS[2][2][DIMD];
    __shared__ float rowS[2][2][DIMD];

    // Stage round 0 (columns 0,1 and rows 0,1).
    if (tx == 0) {
#pragma unroll
        for (int a = 0; a < 8; a++) {
            colS[0][0][R0 + a] = T[a][0];
            colS[0][1][R0 + a] = T[a][1];
        }
    }
    if (ty == 0) {
#pragma unroll
        for (int b = 0; b < 8; b++) {
            rowS[0][0][C0 + b] = T[0][b];
            rowS[0][1][C0 + b] = T[1][b];
        }
    }
    __syncthreads();

#pragma unroll 1
    for (int rq = 0; rq < 16; rq++) {
        gj2_round<0>(T, colS, rowS, rq, ty, tx, R0, C0);
        gj2_round<1>(T, colS, rowS, rq, ty, tx, R0, C0);
        gj2_round<2>(T, colS, rowS, rq, ty, tx, R0, C0);
        gj2_round<3>(T, colS, rowS, rq, ty, tx, R0, C0);
    }

    // Registers now hold inv(A). Emit reciprocal of its diagonal.
    if (ty == tx) {
#pragma unroll
        for (int a = 0; a < 8; a++) {
            g_rdinv[(size_t)(R0 + a) * P + p] = 1.0f / T[a][a];
        }
    }
}

// ---------------------------------------------------------------------------
// Phase B: streaming whitening + cosine similarity.
// 4 lanes cooperate per (b,p) output (32 d's each) + shfl reduction.
// g_rdinv holds 1/diag(inv) => pure multiply, no divisions.
// ---------------------------------------------------------------------------
__global__ void ace_kernel(const float* __restrict__ X,
                           const float* __restrict__ bmean,
                           const float* __restrict__ covs,
                           const float* __restrict__ sig,
                           const int* __restrict__ covtype,
                           float* __restrict__ out,
                           int B, int P)
{
    int gtid = blockIdx.x * blockDim.x + threadIdx.x;
    int idx  = gtid >> 2;            // output index (b*P + p)
    int sub  = gtid & 3;             // which quarter of D this lane handles
    if (idx >= B * P) return;
    int b = idx / P;
    int p = idx - b * P;
    int ct = *covtype;

    float ww = 0.f, ws = 0.f, ss = 0.f;

    if (ct == 0) {
        // Full-covariance fallback: each lane does 32 of the 128 output dims.
        for (int m = sub * 32; m < sub * 32 + 32; m++) {
            float w = 0.f;
            const float* cr = covs + ((size_t)p * DIMD + m) * DIMD;
            for (int d = 0; d < DIMD; d++) {
                float xc = X[((size_t)b * DIMD + d) * P + p] - bmean[(size_t)d * P + p];
                w = fmaf(xc, cr[d], w);
            }
            float s = sig[(size_t)m * P + p];
            ww = fmaf(w, w, ww);
            ws = fmaf(w, s, ws);
            ss = fmaf(s, s, ss);
        }
    } else {
        bool use_diag = (ct == 1);
        int d0 = sub * 32;
#pragma unroll 16
        for (int i = 0; i < 32; i++) {
            int d = d0 + i;
            float xc = X[((size_t)b * DIMD + d) * P + p] - bmean[(size_t)d * P + p];
            float s  = sig[(size_t)d * P + p];
            float w  = use_diag ? (xc * g_rdinv[(size_t)d * P + p]) : xc;
            ww = fmaf(w, w, ww);
            ws = fmaf(w, s, ws);
            ss = fmaf(s, s, ss);
        }
    }

#pragma unroll
    for (int m = 1; m < 4; m <<= 1) {
        ww += __shfl_xor_sync(0xFFFFFFFF, ww, m);
        ws += __shfl_xor_sync(0xFFFFFFFF, ws, m);
        ss += __shfl_xor_sync(0xFFFFFFFF, ss, m);
    }

    if (sub == 0) {
        float denom = fmaxf(sqrtf(ww), 1e-12f) * fmaxf(sqrtf(ss), 1e-12f);
        out[idx] = ws / denom;
    }
}

extern "C" void kernel_launch(void* const* d_in, const int* in_sizes, int n_in,
                              void* d_out, int out_size)
{
    const float* X      = (const float*)d_in[0];
    const float* bmean  = (const float*)d_in[1];
    const float* covs   = (const float*)d_in[2];
    const float* sig    = (const float*)d_in[3];
    const int*   ctype  = (const int*)d_in[4];
    float*       out    = (float*)d_out;

    int P = in_sizes[2] / (DIMD * DIMD);           // 3136
    int B = in_sizes[0] / (DIMD * P);              // 32

    inv_diag_kernel<<<P, 256>>>(covs, P);

    int total = B * P * 4;                         // 4 lanes per output
    ace_kernel<<<(total + 255) / 256, 256>>>(X, bmean, covs, sig, ctype, out, B, P);
}

// round 7
// speedup vs baseline: 1.6390x; 1.3160x over previous
#include <cuda_runtime.h>
#include <math.h>

#define DIMD 128
#define PMAX 3136

typedef unsigned long long ull;

// Scratch: RECIPROCAL of diag(inv(b_covs[p]))[d], stored [D][P].
__device__ float g_rdinv[DIMD * PMAX];

// ---- packed f32x2 helpers (Blackwell sm_103a) ------------------------------
__device__ __forceinline__ ull pack2(float lo, float hi) {
    ull r; asm("mov.b64 %0, {%1, %2};" : "=l"(r) : "f"(lo), "f"(hi)); return r;
}
__device__ __forceinline__ float2 unpack2(ull v) {
    float2 r; asm("mov.b64 {%0, %1}, %2;" : "=f"(r.x), "=f"(r.y) : "l"(v)); return r;
}
__device__ __forceinline__ ull fma2(ull a, ull b, ull c) {
    ull d; asm("fma.rn.f32x2 %0, %1, %2, %3;" : "=l"(d) : "l"(a), "l"(b), "l"(c)); return d;
}
__device__ __forceinline__ ull mul2(ull a, ull b) {
    ull d; asm("mul.rn.f32x2 %0, %1, %2;" : "=l"(d) : "l"(a), "l"(b)); return d;
}
// Fast reciprocal: rcp.approx + 1 Newton step (fp32-accurate, ~4 ops vs ~15
// for IEEE div).
__device__ __forceinline__ float frcp(float x) {
    float r; asm("rcp.approx.ftz.f32 %0, %1;" : "=f"(r) : "f"(x));
    return r * fmaf(-x, r, 2.0f);
}

// ---------------------------------------------------------------------------
// Phase A: Gauss-Jordan inversion (proven R2 skeleton) with the register tile
// held as PACKED f32x2 pairs: 8 rows x 4 packed cols per thread. The rank-1
// update is 32 fma.rn.f32x2 per step instead of 64 FFMA -- 2x issue
// throughput on the fma pipe, which R2 analysis showed is the binding limit.
// Scalar fixups/staging unpack packed halves only on the 16 affected threads.
// ---------------------------------------------------------------------------
template<int KQ>
__device__ __forceinline__ void gj_step(
    ull (&Tp)[8][4],
    float (&colbuf)[2][DIMD], float (&pivbuf)[2][DIMD],
    int kk, int ty, int tx, int R0, int C0)
{
    constexpr int BUF  = KQ & 1;
    constexpr int NBUF = BUF ^ 1;
    const int k = (kk << 3) + KQ;

    float pv  = frcp(colbuf[BUF][k]);
    float npv = -pv;
    ull npv2  = pack2(npv, npv);

    // Pivot column (raw) for this thread's rows.
    float ci[8];
    {
        const float4* c4 = reinterpret_cast<const float4*>(&colbuf[BUF][R0]);
        float4 v0 = c4[0], v1 = c4[1];
        ci[0]=v0.x; ci[1]=v0.y; ci[2]=v0.z; ci[3]=v0.w;
        ci[4]=v1.x; ci[5]=v1.y; ci[6]=v1.z; ci[7]=v1.w;
    }
    ull ci2[8];
#pragma unroll
    for (int a = 0; a < 8; a++) ci2[a] = pack2(ci[a], ci[a]);

    // Pivot row (raw) for this thread's cols, loaded packed.
    ull rj2[4];
    {
        const ulonglong2* r4 = reinterpret_cast<const ulonglong2*>(&pivbuf[BUF][C0]);
        ulonglong2 u0 = r4[0], u1 = r4[1];
        rj2[0]=u0.x; rj2[1]=u0.y; rj2[2]=u1.x; rj2[3]=u1.y;
    }
    ull sn2[4];                       // -(row_k * pv)
#pragma unroll
    for (int b = 0; b < 4; b++) sn2[b] = mul2(rj2[b], npv2);

    // Rank-1 update: T -= ci * s   (32 packed FMAs).
#pragma unroll
    for (int a = 0; a < 8; a++)
#pragma unroll
        for (int b = 0; b < 4; b++)
            Tp[a][b] = fma2(ci2[a], sn2[b], Tp[a][b]);

    // Pivot-row fixup: M[k][j] = row_k[j] * pv.
    if (kk == ty) {
        ull pv2 = pack2(pv, pv);
#pragma unroll
        for (int b = 0; b < 4; b++) Tp[KQ][b] = mul2(rj2[b], pv2);
    }
    // Pivot-col fixup: M[i][k] = -ci[i]*pv; M[k][k] = pv. (After row fixup.)
    if (kk == tx) {
        constexpr int PB = KQ >> 1;
#pragma unroll
        for (int a = 0; a < 8; a++) {
            float2 h = unpack2(Tp[a][PB]);
            float v = (R0 + a == k) ? pv : ci[a] * npv;
            if (KQ & 1) h.y = v; else h.x = v;
            Tp[a][PB] = pack2(h.x, h.y);
        }
    }

    // Stage next pivot column/row from the UPDATED matrix.
    if (k + 1 < DIMD) {
        constexpr int KNQ = (KQ + 1) & 7;
        constexpr int PBN = KNQ >> 1;
        const int kkn = kk + ((KQ + 1) >> 3);
        if (kkn == tx) {
#pragma unroll
            for (int a = 0; a < 8; a++) {
                float2 h = unpack2(Tp[a][PBN]);
                colbuf[NBUF][R0 + a] = (KNQ & 1) ? h.y : h.x;
            }
        }
        if (kkn == ty) {
            ulonglong2* d4 = reinterpret_cast<ulonglong2*>(&pivbuf[NBUF][C0]);
            d4[0] = make_ulonglong2(Tp[KNQ][0], Tp[KNQ][1]);
            d4[1] = make_ulonglong2(Tp[KNQ][2], Tp[KNQ][3]);
        }
    }
    __syncthreads();
}

__global__ __launch_bounds__(256, 2)
void inv_diag_kernel(const float* __restrict__ covs, int P)
{
    int p = blockIdx.x;
    const float* A = covs + (size_t)p * DIMD * DIMD;

    int tid = threadIdx.x;
    int ty = tid >> 4;
    int tx = tid & 15;
    int R0 = ty << 3;
    int C0 = tx << 3;

    ull Tp[8][4];     // 8 rows x 4 packed col-pairs = 8x8 fp32 tile
#pragma unroll
    for (int a = 0; a < 8; a++) {
        const ulonglong2* src =
            reinterpret_cast<const ulonglong2*>(A + (size_t)(R0 + a) * DIMD + C0);
        ulonglong2 v0 = src[0], v1 = src[1];
        Tp[a][0]=v0.x; Tp[a][1]=v0.y; Tp[a][2]=v1.x; Tp[a][3]=v1.y;
    }

    __shared__ __align__(16) float colbuf[2][DIMD];   // raw pivot column M[:,k]
    __shared__ __align__(16) float pivbuf[2][DIMD];   // raw pivot row    M[k,:]

    // Stage step 0.
    if (tx == 0) {
#pragma unroll
        for (int a = 0; a < 8; a++) colbuf[0][R0 + a] = unpack2(Tp[a][0]).x;
    }
    if (ty == 0) {
        ulonglong2* d4 = reinterpret_cast<ulonglong2*>(&pivbuf[0][C0]);
        d4[0] = make_ulonglong2(Tp[0][0], Tp[0][1]);
        d4[1] = make_ulonglong2(Tp[0][2], Tp[0][3]);
    }
    __syncthreads();

#pragma unroll 1
    for (int kk = 0; kk < 16; kk++) {
        gj_step<0>(Tp, colbuf, pivbuf, kk, ty, tx, R0, C0);
        gj_step<1>(Tp, colbuf, pivbuf, kk, ty, tx, R0, C0);
        gj_step<2>(Tp, colbuf, pivbuf, kk, ty, tx, R0, C0);
        gj_step<3>(Tp, colbuf, pivbuf, kk, ty, tx, R0, C0);
        gj_step<4>(Tp, colbuf, pivbuf, kk, ty, tx, R0, C0);
        gj_step<5>(Tp, colbuf, pivbuf, kk, ty, tx, R0, C0);
        gj_step<6>(Tp, colbuf, pivbuf, kk, ty, tx, R0, C0);
        gj_step<7>(Tp, colbuf, pivbuf, kk, ty, tx, R0, C0);
    }

    // Registers now hold inv(A). Emit reciprocal of its diagonal.
    if (ty == tx) {
#pragma unroll
        for (int a = 0; a < 8; a++) {
            float2 h = unpack2(Tp[a][a >> 1]);
            float dv = (a & 1) ? h.y : h.x;
            g_rdinv[(size_t)(R0 + a) * P + p] = frcp(dv);
        }
    }
}

// ---------------------------------------------------------------------------
// Phase B: streaming whitening + cosine similarity.
// 4 lanes cooperate per (b,p) output (32 d's each) + shfl reduction.
// g_rdinv holds 1/diag(inv) => pure multiply, no divisions.
// ---------------------------------------------------------------------------
__global__ void ace_kernel(const float* __restrict__ X,
                           const float* __restrict__ bmean,
                           const float* __restrict__ covs,
                           const float* __restrict__ sig,
                           const int* __restrict__ covtype,
                           float* __restrict__ out,
                           int B, int P)
{
    int gtid = blockIdx.x * blockDim.x + threadIdx.x;
    int idx  = gtid >> 2;            // output index (b*P + p)
    int sub  = gtid & 3;             // which quarter of D this lane handles
    if (idx >= B * P) return;
    int b = idx / P;
    int p = idx - b * P;
    int ct = *covtype;

    float ww = 0.f, ws = 0.f, ss = 0.f;

    if (ct == 0) {
        // Full-covariance fallback: each lane does 32 of the 128 output dims.
        for (int m = sub * 32; m < sub * 32 + 32; m++) {
            float w = 0.f;
            const float* cr = covs + ((size_t)p * DIMD + m) * DIMD;
            for (int d = 0; d < DIMD; d++) {
                float xc = X[((size_t)b * DIMD + d) * P + p] - bmean[(size_t)d * P + p];
                w = fmaf(xc, cr[d], w);
            }
            float s = sig[(size_t)m * P + p];
            ww = fmaf(w, w, ww);
            ws = fmaf(w, s, ws);
            ss = fmaf(s, s, ss);
        }
    } else {
        bool use_diag = (ct == 1);
        int d0 = sub * 32;
#pragma unroll 16
        for (int i = 0; i < 32; i++) {
            int d = d0 + i;
            float xc = X[((size_t)b * DIMD + d) * P + p] - bmean[(size_t)d * P + p];
            float s  = sig[(size_t)d * P + p];
            float w  = use_diag ? (xc * g_rdinv[(size_t)d * P + p]) : xc;
            ww = fmaf(w, w, ww);
            ws = fmaf(w, s, ws);
            ss = fmaf(s, s, ss);
        }
    }

#pragma unroll
    for (int m = 1; m < 4; m <<= 1) {
        ww += __shfl_xor_sync(0xFFFFFFFF, ww, m);
        ws += __shfl_xor_sync(0xFFFFFFFF, ws, m);
        ss += __shfl_xor_sync(0xFFFFFFFF, ss, m);
    }

    if (sub == 0) {
        float denom = fmaxf(sqrtf(ww), 1e-12f) * fmaxf(sqrtf(ss), 1e-12f);
        out[idx] = ws / denom;
    }
}

extern "C" void kernel_launch(void* const* d_in, const int* in_sizes, int n_in,
                              void* d_out, int out_size)
{
    const float* X      = (const float*)d_in[0];
    const float* bmean  = (const float*)d_in[1];
    const float* covs   = (const float*)d_in[2];
    const float* sig    = (const float*)d_in[3];
    const int*   ctype  = (const int*)d_in[4];
    float*       out    = (float*)d_out;

    int P = in_sizes[2] / (DIMD * DIMD);           // 3136
    int B = in_sizes[0] / (DIMD * P);              // 32

    inv_diag_kernel<<<P, 256>>>(covs, P);

    int total = B * P * 4;                         // 4 lanes per output
    ace_kernel<<<(total + 255) / 256, 256>>>(X, bmean, covs, sig, ctype, out, B, P);
}